// round 3
// baseline (speedup 1.0000x reference)
#include <cuda_runtime.h>
#include <math.h>
#include <stdint.h>

// ---------------- problem constants ----------------
#define NN 50000
#define DHID 128
#define DOUT 64
#define NGRAPH 16
#define BN_EPS 1e-5f

// ---------------- device scratch (statically allocated; no cudaMalloc) ------
__device__ __align__(16) float g_dinv[NN];
__device__ __align__(16) float g_bufA[NN * DHID];
__device__ __align__(16) float g_bufB[NN * DHID];
__device__ __align__(16) float g_bnsum[DHID];
__device__ __align__(16) float g_bnsq[DHID];
__device__ __align__(16) float g_pool[NGRAPH * DOUT];
__device__ __align__(16) float g_pcnt[NGRAPH];

// ---------------- init: deg=1 (self loop), zero pool/cnt ----------------
__global__ void k_init(int n) {
    int i = blockIdx.x * blockDim.x + threadIdx.x;
    if (i < n) g_dinv[i] = 1.0f;
    if (i < NGRAPH * DOUT) g_pool[i] = 0.0f;
    if (i < NGRAPH) g_pcnt[i] = 0.0f;
}

// ---------------- degree accumulate over dst (int32 indices) ----------------
__global__ void k_deg(const int* __restrict__ dst, int e, int n) {
    int i = blockIdx.x * blockDim.x + threadIdx.x;
    if (i < e) {
        int d = dst[i];
        if ((unsigned)d < (unsigned)n) atomicAdd(&g_dinv[d], 1.0f);
    }
}

// ---------------- deg -> rsqrt(deg) in place ----------------
__global__ void k_dinv(int n) {
    int i = blockIdx.x * blockDim.x + threadIdx.x;
    if (i < n) g_dinv[i] = rsqrtf(g_dinv[i]);
}

// ---------------- GEMM: OUT[n,NOUT] = X[n,K] @ W[K,NOUT] ----------------
// One warp computes 4 rows x NOUT cols.
template <int K, int NOUT>
__global__ void k_gemm(const float* __restrict__ X, const float* __restrict__ W,
                       float* __restrict__ OUT, int nrows) {
    constexpr int CPL = NOUT / 32;  // cols per lane (4 or 2)
    constexpr int R = 4;
    int warp = (blockIdx.x * blockDim.x + threadIdx.x) >> 5;
    int lane = threadIdx.x & 31;
    int row0 = warp * R;
    if (row0 >= nrows) return;
    const int colbase = lane * CPL;

    float acc[R][CPL];
#pragma unroll
    for (int r = 0; r < R; r++)
#pragma unroll
        for (int c = 0; c < CPL; c++) acc[r][c] = 0.0f;

#pragma unroll 2
    for (int k = 0; k < K; k += 4) {
        float xv[R][4];
#pragma unroll
        for (int r = 0; r < R; r++) {
            float4 t = *reinterpret_cast<const float4*>(&X[(size_t)(row0 + r) * K + k]);
            xv[r][0] = t.x; xv[r][1] = t.y; xv[r][2] = t.z; xv[r][3] = t.w;
        }
#pragma unroll
        for (int kk = 0; kk < 4; kk++) {
            float wv[CPL];
            if constexpr (CPL == 4) {
                float4 t = *reinterpret_cast<const float4*>(&W[(size_t)(k + kk) * NOUT + colbase]);
                wv[0] = t.x; wv[1] = t.y; wv[2] = t.z; wv[3] = t.w;
            } else {
                float2 t = *reinterpret_cast<const float2*>(&W[(size_t)(k + kk) * NOUT + colbase]);
                wv[0] = t.x; wv[1] = t.y;
            }
#pragma unroll
            for (int r = 0; r < R; r++)
#pragma unroll
                for (int c = 0; c < CPL; c++) acc[r][c] += xv[r][kk] * wv[c];
        }
    }
#pragma unroll
    for (int r = 0; r < R; r++) {
        int row = row0 + r;
        if (row < nrows) {
#pragma unroll
            for (int c = 0; c < CPL; c++)
                OUT[(size_t)row * NOUT + colbase + c] = acc[r][c];
        }
    }
}

// ---------------- self-loop init: out = h * dinv^2 (also avoids zero-fill) --
template <int NOUT>
__global__ void k_selfinit(const float* __restrict__ h, float* __restrict__ out, int n) {
    int idx = blockIdx.x * blockDim.x + threadIdx.x;  // float4 index
    int total = n * (NOUT / 4);
    if (idx >= total) return;
    int row = idx / (NOUT / 4);
    float s = g_dinv[row];
    s = s * s;
    float4 v = reinterpret_cast<const float4*>(h)[idx];
    v.x *= s; v.y *= s; v.z *= s; v.w *= s;
    reinterpret_cast<float4*>(out)[idx] = v;
}

// ---------------- edge scatter: out[d] += h[s] * dinv[s]*dinv[d] ------------
// Vector reduction (red.global.add.v4.f32) with cvta'd global address.
template <int NOUT>
__global__ void k_scatter(const int* __restrict__ src, const int* __restrict__ dst,
                          const float* __restrict__ h, float* __restrict__ out,
                          int e_total, int n) {
    constexpr int LPE = NOUT / 4;   // lanes per edge
    constexpr int EPW = 32 / LPE;   // edges per warp
    int warp = (blockIdx.x * blockDim.x + threadIdx.x) >> 5;
    int lane = threadIdx.x & 31;
    int e = warp * EPW + lane / LPE;
    if (e >= e_total) return;
    int s = src[e];
    int d = dst[e];
    if ((unsigned)s >= (unsigned)n || (unsigned)d >= (unsigned)n) return;
    float w = g_dinv[s] * g_dinv[d];
    int c = (lane % LPE) * 4;
    float4 v = *reinterpret_cast<const float4*>(&h[(size_t)s * NOUT + c]);
    unsigned long long gp =
        (unsigned long long)__cvta_generic_to_global(&out[(size_t)d * NOUT + c]);
    asm volatile("red.global.add.v4.f32 [%0], {%1,%2,%3,%4};"
                 :: "l"(gp), "f"(v.x * w), "f"(v.y * w), "f"(v.z * w), "f"(v.w * w)
                 : "memory");
}

// ---------------- BN: zero stats ----------------
__global__ void k_bnzero() {
    g_bnsum[threadIdx.x] = 0.0f;
    g_bnsq[threadIdx.x] = 0.0f;
}

// ---------------- BN: column sums / sumsq ----------------
__global__ void k_bnstats(const float* __restrict__ a, int n) {
    int col = threadIdx.x;  // 128
    float s = 0.0f, q = 0.0f;
    int stride = gridDim.x * blockDim.y;
    for (int r = blockIdx.x * blockDim.y + threadIdx.y; r < n; r += stride) {
        float v = a[(size_t)r * DHID + col];
        s += v;
        q += v * v;
    }
    atomicAdd(&g_bnsum[col], s);
    atomicAdd(&g_bnsq[col], q);
}

// ---------------- BN: finalize to (scale, shift) in place -------------------
__global__ void k_bnfinal(const float* __restrict__ gam, const float* __restrict__ bet, float n) {
    int c = threadIdx.x;  // 128
    float mu = g_bnsum[c] / n;
    float var = g_bnsq[c] / n - mu * mu;
    float sc = rsqrtf(var + BN_EPS) * gam[c];
    g_bnsum[c] = sc;
    g_bnsq[c] = bet[c] - mu * sc;
}

// ---------------- BN apply + ReLU (in place) ----------------
__global__ void k_bnapply(float* __restrict__ a, int n) {
    int idx = blockIdx.x * blockDim.x + threadIdx.x;  // float4 index
    int total = n * (DHID / 4);
    if (idx >= total) return;
    int c = (idx & (DHID / 4 - 1)) * 4;
    float4 v = reinterpret_cast<const float4*>(a)[idx];
    v.x = fmaxf(v.x * g_bnsum[c + 0] + g_bnsq[c + 0], 0.0f);
    v.y = fmaxf(v.y * g_bnsum[c + 1] + g_bnsq[c + 1], 0.0f);
    v.z = fmaxf(v.z * g_bnsum[c + 2] + g_bnsq[c + 2], 0.0f);
    v.w = fmaxf(v.w * g_bnsum[c + 3] + g_bnsq[c + 3], 0.0f);
    reinterpret_cast<float4*>(a)[idx] = v;
}

// ---------------- pool: batch is sorted -> run-length accumulate ------------
#define POOL_CHUNK 128
__global__ void k_pool(const float* __restrict__ h, const int* __restrict__ batch, int n) {
    int col = threadIdx.x;  // 64
    int r0 = blockIdx.x * POOL_CHUNK;
    if (r0 >= n) return;
    int r1 = min(r0 + POOL_CHUNK, n);
    int cur = batch[r0] & (NGRAPH - 1);
    float acc = 0.0f, cacc = 0.0f;
    for (int r = r0; r < r1; r++) {
        int g = batch[r] & (NGRAPH - 1);
        if (g != cur) {
            atomicAdd(&g_pool[cur * DOUT + col], acc);
            if (col == 0) atomicAdd(&g_pcnt[cur], cacc);
            acc = 0.0f; cacc = 0.0f; cur = g;
        }
        acc += h[(size_t)r * DOUT + col];
        cacc += 1.0f;
    }
    atomicAdd(&g_pool[cur * DOUT + col], acc);
    if (col == 0) atomicAdd(&g_pcnt[cur], cacc);
}

// ---------------- final: divide, add b3 ----------------
__global__ void k_final(float* __restrict__ out, const float* __restrict__ b3) {
    int t = threadIdx.x;  // 1024
    int g = t / DOUT;
    int c = t % DOUT;
    float cnt = g_pcnt[g];
    out[t] = (cnt > 0.0f) ? (g_pool[t] / cnt + b3[c]) : 0.0f;
}

// ============================================================================
extern "C" void kernel_launch(void* const* d_in, const int* in_sizes, int n_in,
                              void* d_out, int out_size) {
    const float* x     = (const float*)d_in[0];
    const int*   ei    = (const int*)d_in[1];      // int64 coerced to int32 by harness
    const int*   batch = (const int*)d_in[2];
    const float* W1    = (const float*)d_in[3];
    // b1 (d_in[4]) cancels under BN1
    const float* W2    = (const float*)d_in[5];
    // b2 (d_in[6]) cancels under BN2
    const float* W3    = (const float*)d_in[7];
    const float* b3    = (const float*)d_in[8];
    const float* g1    = (const float*)d_in[9];
    const float* be1   = (const float*)d_in[10];
    const float* g2    = (const float*)d_in[11];
    const float* be2   = (const float*)d_in[12];
    float* out = (float*)d_out;

    const int n = in_sizes[2];       // 50000
    const int E = in_sizes[1] / 2;   // 800000
    const int* src = ei;
    const int* dst = ei + E;

    float* bufA; float* bufB;
    cudaGetSymbolAddress((void**)&bufA, g_bufA);
    cudaGetSymbolAddress((void**)&bufB, g_bufB);

    const int TB = 256;
    int nb_n   = (n + TB - 1) / TB;
    int nb_e   = (E + TB - 1) / TB;
    int gemm_warps = (n + 3) / 4;
    int nb_gemm = (gemm_warps * 32 + TB - 1) / TB;
    int nb_si128 = (n * (DHID / 4) + TB - 1) / TB;
    int nb_si64  = (n * (DOUT / 4) + TB - 1) / TB;
    int nb_sc128 = (int)(((long long)E * 32 + TB - 1) / TB);             // 1 edge/warp
    int nb_sc64  = (int)((((long long)(E + 1) / 2) * 32 + TB - 1) / TB); // 2 edges/warp
    dim3 bn_block(DHID, 4);
    int nb_stats = 256;
    int nb_pool  = (n + POOL_CHUNK - 1) / POOL_CHUNK;

    // degree / norm
    k_init<<<nb_n, TB>>>(n);
    k_deg<<<nb_e, TB>>>(dst, E, n);
    k_dinv<<<nb_n, TB>>>(n);

    // ---- layer 1: x[*,256] @ W1 -> 128, aggregate, BN+ReLU ----
    k_gemm<256, 128><<<nb_gemm, TB>>>(x, W1, bufA, n);
    k_selfinit<128><<<nb_si128, TB>>>(bufA, bufB, n);
    k_scatter<128><<<nb_sc128, TB>>>(src, dst, bufA, bufB, E, n);
    k_bnzero<<<1, DHID>>>();
    k_bnstats<<<nb_stats, bn_block>>>(bufB, n);
    k_bnfinal<<<1, DHID>>>(g1, be1, (float)n);
    k_bnapply<<<nb_si128, TB>>>(bufB, n);

    // ---- layer 2: 128 -> 128 ----
    k_gemm<128, 128><<<nb_gemm, TB>>>(bufB, W2, bufA, n);
    k_selfinit<128><<<nb_si128, TB>>>(bufA, bufB, n);
    k_scatter<128><<<nb_sc128, TB>>>(src, dst, bufA, bufB, E, n);
    k_bnzero<<<1, DHID>>>();
    k_bnstats<<<nb_stats, bn_block>>>(bufB, n);
    k_bnfinal<<<1, DHID>>>(g2, be2, (float)n);
    k_bnapply<<<nb_si128, TB>>>(bufB, n);

    // ---- layer 3: 128 -> 64, aggregate (b3 folded into final) ----
    k_gemm<128, 64><<<nb_gemm, TB>>>(bufB, W3, bufA, n);
    k_selfinit<64><<<nb_si64, TB>>>(bufA, bufB, n);
    k_scatter<64><<<nb_sc64, TB>>>(src, dst, bufA, bufB, E, n);

    // ---- mean pool + bias ----
    k_pool<<<nb_pool, DOUT>>>(bufB, batch, n);
    k_final<<<1, NGRAPH * DOUT>>>(out, b3);
}

// round 4
// speedup vs baseline: 1.1917x; 1.1917x over previous
#include <cuda_runtime.h>
#include <math.h>
#include <stdint.h>

// ---------------- problem constants ----------------
#define NN 50000
#define DHID 128
#define DOUT 64
#define NGRAPH 16
#define BN_EPS 1e-5f

// ---------------- device scratch ----------------
__device__ __align__(16) float g_dinv[NN];
__device__ __align__(16) float g_bufA[NN * DHID];
__device__ __align__(16) float g_bufB[NN * DHID];
__device__ __align__(16) float g_bnsum[DHID];
__device__ __align__(16) float g_bnsq[DHID];
__device__ __align__(16) float g_pool[NGRAPH * DOUT];
__device__ __align__(16) float g_pcnt[NGRAPH];

// ---------------- init: deg=1 (self loop), zero pool/cnt ----------------
__global__ void k_init(int n) {
    int i = blockIdx.x * blockDim.x + threadIdx.x;
    if (i < n) g_dinv[i] = 1.0f;
    if (i < NGRAPH * DOUT) g_pool[i] = 0.0f;
    if (i < NGRAPH) g_pcnt[i] = 0.0f;
}

__global__ void k_deg(const int* __restrict__ dst, int e, int n) {
    int i = blockIdx.x * blockDim.x + threadIdx.x;
    if (i < e) {
        int d = dst[i];
        if ((unsigned)d < (unsigned)n) atomicAdd(&g_dinv[d], 1.0f);
    }
}

__global__ void k_dinv(int n) {
    int i = blockIdx.x * blockDim.x + threadIdx.x;
    if (i < n) g_dinv[i] = rsqrtf(g_dinv[i]);
}

// ---------------- tiled GEMM with FFMA2 + fused BN/ReLU + fused selfinit ----
// OUT_raw[n,NOUT] = T(X)[n,K] @ W[K,NOUT];  OUT_scaled = OUT_raw * dinv[row]^2
// T = identity or BN-affine+ReLU (scale/shift from g_bnsum/g_bnsq).
// Block: 256 threads = 16x16; block tile 128 x NOUT; thread tile 8 x TN.
// Inner product uses fma.rn.f32x2 (row-paired accumulators).
template <int KDIM, int NOUT, bool BNRELU>
__global__ void __launch_bounds__(256, 2)
k_gemm_t(const float* X, const float* __restrict__ W,
         float* __restrict__ OUT_raw, float* OUT_scaled, int nrows) {
    constexpr int BM = 128, BK = 16;
    constexpr int TN = NOUT / 16;           // 8 or 4
    __shared__ float Xs[BK][BM + 4];
    __shared__ float Ws[BK][NOUT];

    const int tid = threadIdx.x;
    const int tx = tid & 15, ty = tid >> 4;
    const int row0 = blockIdx.x * BM;

    // acc2[rp][c] packs rows (2rp, 2rp+1) for column c
    unsigned long long acc2[4][TN];
#pragma unroll
    for (int rp = 0; rp < 4; rp++)
#pragma unroll
        for (int c = 0; c < TN; c++) acc2[rp][c] = 0ull;

    const int xr = tid >> 2;            // 0..63
    const int kq = (tid & 3) * 4;       // 0,4,8,12

    for (int kb = 0; kb < KDIM; kb += BK) {
        // ---- X tile (with optional BN+ReLU transform) ----
        float sc[4], sh[4];
        if (BNRELU) {
#pragma unroll
            for (int j = 0; j < 4; j++) {
                sc[j] = g_bnsum[kb + kq + j];
                sh[j] = g_bnsq[kb + kq + j];
            }
        }
#pragma unroll
        for (int i = 0; i < 2; i++) {
            int r = xr + i * 64;
            int row = row0 + r;
            float4 v = make_float4(0.f, 0.f, 0.f, 0.f);
            if (row < nrows)
                v = *reinterpret_cast<const float4*>(&X[(size_t)row * KDIM + kb + kq]);
            if (BNRELU) {
                v.x = fmaxf(fmaf(v.x, sc[0], sh[0]), 0.f);
                v.y = fmaxf(fmaf(v.y, sc[1], sh[1]), 0.f);
                v.z = fmaxf(fmaf(v.z, sc[2], sh[2]), 0.f);
                v.w = fmaxf(fmaf(v.w, sc[3], sh[3]), 0.f);
            }
            Xs[kq + 0][r] = v.x;
            Xs[kq + 1][r] = v.y;
            Xs[kq + 2][r] = v.z;
            Xs[kq + 3][r] = v.w;
        }
        // ---- W tile (row-major already k-major) ----
#pragma unroll
        for (int i = 0; i < (BK * NOUT / 4) / 256; i++) {
            int idx = tid + i * 256;
            int k = idx / (NOUT / 4);
            int c = (idx % (NOUT / 4)) * 4;
            *reinterpret_cast<float4*>(&Ws[k][c]) =
                *reinterpret_cast<const float4*>(&W[(size_t)(kb + k) * NOUT + c]);
        }
        __syncthreads();

        // ---- compute ----
#pragma unroll
        for (int k = 0; k < BK; k++) {
            // row pairs directly from LDS.128
            unsigned long long xv2[4];
            {
                float4 a = *reinterpret_cast<const float4*>(&Xs[k][ty * 8]);
                float4 b = *reinterpret_cast<const float4*>(&Xs[k][ty * 8 + 4]);
                xv2[0] = *reinterpret_cast<unsigned long long*>(&a.x);
                xv2[1] = *reinterpret_cast<unsigned long long*>(&a.z);
                xv2[2] = *reinterpret_cast<unsigned long long*>(&b.x);
                xv2[3] = *reinterpret_cast<unsigned long long*>(&b.z);
            }
            float wv[TN];
            *reinterpret_cast<float4*>(&wv[0]) =
                *reinterpret_cast<const float4*>(&Ws[k][tx * TN]);
            if (TN == 8)
                *reinterpret_cast<float4*>(&wv[4]) =
                    *reinterpret_cast<const float4*>(&Ws[k][tx * TN + 4]);
#pragma unroll
            for (int c = 0; c < TN; c++) {
                unsigned long long wd;
                asm("mov.b64 %0, {%1, %1};" : "=l"(wd) : "f"(wv[c]));
#pragma unroll
                for (int rp = 0; rp < 4; rp++) {
                    asm("fma.rn.f32x2 %0, %1, %2, %0;"
                        : "+l"(acc2[rp][c]) : "l"(xv2[rp]), "l"(wd));
                }
            }
        }
        __syncthreads();
    }

    // ---- epilogue: raw + dinv^2-scaled ----
#pragma unroll
    for (int r = 0; r < 8; r++) {
        int row = row0 + ty * 8 + r;
        if (row >= nrows) break;
        int rp = r >> 1, hi = r & 1;
        float di = g_dinv[row];
        di *= di;
#pragma unroll
        for (int c0 = 0; c0 < TN; c0 += 4) {
            float vals[4];
#pragma unroll
            for (int j = 0; j < 4; j++) {
                float2 p = *reinterpret_cast<float2*>(&acc2[rp][c0 + j]);
                vals[j] = hi ? p.y : p.x;
            }
            float4 raw = make_float4(vals[0], vals[1], vals[2], vals[3]);
            size_t off = (size_t)row * NOUT + tx * TN + c0;
            *reinterpret_cast<float4*>(&OUT_raw[off]) = raw;
            float4 s4 = make_float4(raw.x * di, raw.y * di, raw.z * di, raw.w * di);
            *reinterpret_cast<float4*>(&OUT_scaled[off]) = s4;
        }
    }
}

// ---------------- edge scatter: out[d] += h[s] * dinv[s]*dinv[d] ------------
template <int NOUT>
__global__ void k_scatter(const int* __restrict__ src, const int* __restrict__ dst,
                          const float* __restrict__ h, float* __restrict__ out,
                          int e_total, int n) {
    constexpr int LPE = NOUT / 4;
    constexpr int EPW = 32 / LPE;
    int warp = (blockIdx.x * blockDim.x + threadIdx.x) >> 5;
    int lane = threadIdx.x & 31;
    int e = warp * EPW + lane / LPE;
    if (e >= e_total) return;
    int s = src[e];
    int d = dst[e];
    if ((unsigned)s >= (unsigned)n || (unsigned)d >= (unsigned)n) return;
    float w = g_dinv[s] * g_dinv[d];
    int c = (lane % LPE) * 4;
    float4 v = *reinterpret_cast<const float4*>(&h[(size_t)s * NOUT + c]);
    unsigned long long gp =
        (unsigned long long)__cvta_generic_to_global(&out[(size_t)d * NOUT + c]);
    asm volatile("red.global.add.v4.f32 [%0], {%1,%2,%3,%4};"
                 :: "l"(gp), "f"(v.x * w), "f"(v.y * w), "f"(v.z * w), "f"(v.w * w)
                 : "memory");
}

// ---------------- BN ----------------
__global__ void k_bnzero() {
    g_bnsum[threadIdx.x] = 0.0f;
    g_bnsq[threadIdx.x] = 0.0f;
}

__global__ void k_bnstats(const float* __restrict__ a, int n) {
    int col = threadIdx.x;  // 128
    float s = 0.0f, q = 0.0f;
    int stride = gridDim.x * blockDim.y;
    for (int r = blockIdx.x * blockDim.y + threadIdx.y; r < n; r += stride) {
        float v = a[(size_t)r * DHID + col];
        s += v;
        q += v * v;
    }
    atomicAdd(&g_bnsum[col], s);
    atomicAdd(&g_bnsq[col], q);
}

__global__ void k_bnfinal(const float* __restrict__ gam, const float* __restrict__ bet, float n) {
    int c = threadIdx.x;  // 128
    float mu = g_bnsum[c] / n;
    float var = g_bnsq[c] / n - mu * mu;
    float sc = rsqrtf(var + BN_EPS) * gam[c];
    g_bnsum[c] = sc;
    g_bnsq[c] = bet[c] - mu * sc;
}

// ---------------- pool: batch sorted -> run-length accumulate ----------------
#define POOL_CHUNK 128
__global__ void k_pool(const float* __restrict__ h, const int* __restrict__ batch, int n) {
    int col = threadIdx.x;  // 64
    int r0 = blockIdx.x * POOL_CHUNK;
    if (r0 >= n) return;
    int r1 = min(r0 + POOL_CHUNK, n);
    int cur = batch[r0] & (NGRAPH - 1);
    float acc = 0.0f, cacc = 0.0f;
    for (int r = r0; r < r1; r++) {
        int g = batch[r] & (NGRAPH - 1);
        if (g != cur) {
            atomicAdd(&g_pool[cur * DOUT + col], acc);
            if (col == 0) atomicAdd(&g_pcnt[cur], cacc);
            acc = 0.0f; cacc = 0.0f; cur = g;
        }
        acc += h[(size_t)r * DOUT + col];
        cacc += 1.0f;
    }
    atomicAdd(&g_pool[cur * DOUT + col], acc);
    if (col == 0) atomicAdd(&g_pcnt[cur], cacc);
}

__global__ void k_final(float* __restrict__ out, const float* __restrict__ b3) {
    int t = threadIdx.x;  // 1024
    int g = t / DOUT;
    int c = t % DOUT;
    float cnt = g_pcnt[g];
    out[t] = (cnt > 0.0f) ? (g_pool[t] / cnt + b3[c]) : 0.0f;
}

// ============================================================================
extern "C" void kernel_launch(void* const* d_in, const int* in_sizes, int n_in,
                              void* d_out, int out_size) {
    const float* x     = (const float*)d_in[0];
    const int*   ei    = (const int*)d_in[1];   // int64 coerced to int32 by harness
    const int*   batch = (const int*)d_in[2];
    const float* W1    = (const float*)d_in[3];
    const float* W2    = (const float*)d_in[5];
    const float* W3    = (const float*)d_in[7];
    const float* b3    = (const float*)d_in[8];
    const float* g1    = (const float*)d_in[9];
    const float* be1   = (const float*)d_in[10];
    const float* g2    = (const float*)d_in[11];
    const float* be2   = (const float*)d_in[12];
    float* out = (float*)d_out;

    const int n = in_sizes[2];       // 50000
    const int E = in_sizes[1] / 2;   // 800000
    const int* src = ei;
    const int* dst = ei + E;

    float* bufA; float* bufB;
    cudaGetSymbolAddress((void**)&bufA, g_bufA);
    cudaGetSymbolAddress((void**)&bufB, g_bufB);
    float* raw3 = bufA;                 // layer-3 raw gemm output (stride 64)
    float* agg3 = bufA + (size_t)NN * DOUT;  // layer-3 aggregation buffer

    const int TB = 256;
    int nb_n    = (n + TB - 1) / TB;
    int nb_e    = (E + TB - 1) / TB;
    int nb_gemm = (n + 127) / 128;
    int nb_sc128 = (int)(((long long)E * 32 + TB - 1) / TB);             // 1 edge/warp
    int nb_sc64  = (int)((((long long)(E + 1) / 2) * 32 + TB - 1) / TB); // 2 edges/warp
    dim3 bn_block(DHID, 4);
    int nb_stats = 256;
    int nb_pool  = (n + POOL_CHUNK - 1) / POOL_CHUNK;

    // degree / norm
    k_init<<<nb_n, TB>>>(n);
    k_deg<<<nb_e, TB>>>(dst, E, n);
    k_dinv<<<nb_n, TB>>>(n);

    // ---- layer 1: gemm (raw->A, selfinit->B), scatter, BN stats ----
    k_gemm_t<256, 128, false><<<nb_gemm, 256>>>(x, W1, bufA, bufB, n);
    k_scatter<128><<<nb_sc128, TB>>>(src, dst, bufA, bufB, E, n);
    k_bnzero<<<1, DHID>>>();
    k_bnstats<<<nb_stats, bn_block>>>(bufB, n);
    k_bnfinal<<<1, DHID>>>(g1, be1, (float)n);

    // ---- layer 2: gemm fuses BN1+ReLU on load; scaled written in-place ----
    k_gemm_t<128, 128, true><<<nb_gemm, 256>>>(bufB, W2, bufA, bufB, n);
    k_scatter<128><<<nb_sc128, TB>>>(src, dst, bufA, bufB, E, n);
    k_bnzero<<<1, DHID>>>();
    k_bnstats<<<nb_stats, bn_block>>>(bufB, n);
    k_bnfinal<<<1, DHID>>>(g2, be2, (float)n);

    // ---- layer 3: gemm fuses BN2+ReLU; raw->bufA, selfinit->agg3 ----
    k_gemm_t<128, 64, true><<<nb_gemm, 256>>>(bufB, W3, raw3, agg3, n);
    k_scatter<64><<<nb_sc64, TB>>>(src, dst, raw3, agg3, E, n);

    // ---- mean pool + bias ----
    k_pool<<<nb_pool, DOUT>>>(agg3, batch, n);
    k_final<<<1, NGRAPH * DOUT>>>(out, b3);
}